// round 4
// baseline (speedup 1.0000x reference)
#include <cuda_runtime.h>
#include <cuda_bf16.h>
#include <cstdint>

// Problem constants (from reference)
#define VOCAB   1000000
#define EMB     50
#define OUTD    2
#define BATCH   128
#define SEQ     2000

#define NCHUNK  16                   // seq split
#define TOK_PER_CHUNK (SEQ / NCHUNK) // 125
#define YDIM    8                    // tokens processed in parallel per block

// Partial pooled sums: [chunk][batch][EMB]
__device__ float g_scratch[NCHUNK * BATCH * EMB];

// ---------------------------------------------------------------------------
// Kernel 1: gather + partial sum.
// grid  = (BATCH, NCHUNK), block = (EMB=50, YDIM=8) -> 400 threads
// ---------------------------------------------------------------------------
__global__ void partial_kernel(const int* __restrict__ t,
                               const float* __restrict__ emb)
{
    const int b     = blockIdx.x;
    const int chunk = blockIdx.y;
    const int tx    = threadIdx.x;            // embedding component [0,50)
    const int ty    = threadIdx.y;            // token lane [0,8)
    const int tid   = ty * EMB + tx;          // [0,400)

    __shared__ int   sidx[TOK_PER_CHUNK];
    __shared__ float red[YDIM][EMB];

    // Stage indices into shared (int32; -1 padding preserved).
    const int* tptr = t + (size_t)b * SEQ + (size_t)chunk * TOK_PER_CHUNK;
    for (int i = tid; i < TOK_PER_CHUNK; i += EMB * YDIM) {
        sidx[i] = tptr[i];
    }
    __syncthreads();

    float acc = 0.0f;
    #pragma unroll 4
    for (int i = ty; i < TOK_PER_CHUNK; i += YDIM) {
        int idx = sidx[i];
        // mask (reference skips t == -1); upper bound guards against any
        // dtype-contract surprise turning into an illegal access.
        if (idx >= 0 && idx < VOCAB) {
            acc += __ldg(&emb[(size_t)idx * EMB + tx]);
        }
    }

    red[ty][tx] = acc;
    __syncthreads();

    if (ty == 0) {
        float s = acc;
        #pragma unroll
        for (int r = 1; r < YDIM; r++) s += red[r][tx];
        g_scratch[((size_t)chunk * BATCH + b) * EMB + tx] = s;
    }
}

// ---------------------------------------------------------------------------
// Kernel 2: reduce chunks, /BATCH, GEMV [50->2], +bias, ReLU.
// grid = BATCH, block = 64 (50 active)
// ---------------------------------------------------------------------------
__global__ void finalize_kernel(const float* __restrict__ W,
                                const float* __restrict__ bias,
                                float* __restrict__ out)
{
    const int b = blockIdx.x;
    const int c = threadIdx.x;   // [0,64)

    __shared__ float s0[64];
    __shared__ float s1[64];

    float a0 = 0.0f, a1 = 0.0f;
    if (c < EMB) {
        float p = 0.0f;
        #pragma unroll
        for (int k = 0; k < NCHUNK; k++) {
            p += g_scratch[((size_t)k * BATCH + b) * EMB + c];
        }
        p *= (1.0f / (float)BATCH);
        a0 = p * W[c];           // W[0][c]
        a1 = p * W[EMB + c];     // W[1][c]
    }
    s0[c] = a0;
    s1[c] = a1;
    __syncthreads();

    #pragma unroll
    for (int off = 32; off > 0; off >>= 1) {
        if (c < off) {
            s0[c] += s0[c + off];
            s1[c] += s1[c + off];
        }
        __syncthreads();
    }

    if (c == 0) {
        out[b * OUTD + 0] = fmaxf(s0[0] + bias[0], 0.0f);
        out[b * OUTD + 1] = fmaxf(s1[0] + bias[1], 0.0f);
    }
}

// ---------------------------------------------------------------------------
// Inputs (metadata order): t [128,2000] int32 (harness dtype), embeddings
// [1e6,50] f32, W [2,50] f32, b [2] f32.  Output: [128,2] f32.
// ---------------------------------------------------------------------------
extern "C" void kernel_launch(void* const* d_in, const int* in_sizes, int n_in,
                              void* d_out, int out_size)
{
    const int*   t   = (const int*)d_in[0];
    const float* emb = (const float*)d_in[1];
    const float* W   = (const float*)d_in[2];
    const float* bia = (const float*)d_in[3];
    float*       out = (float*)d_out;

    dim3 grid1(BATCH, NCHUNK);
    dim3 block1(EMB, YDIM);
    partial_kernel<<<grid1, block1>>>(t, emb);

    finalize_kernel<<<BATCH, 64>>>(W, bia, out);
}

// round 5
// speedup vs baseline: 1.4545x; 1.4545x over previous
#include <cuda_runtime.h>
#include <cuda_bf16.h>
#include <cstdint>

#define VOCAB   1000000
#define EMB     50
#define OUTD    2
#define BATCH   128
#define SEQ     2000

#define NCHUNK  25                   // seq split
#define TOK     (SEQ / NCHUNK)       // 80 tokens per block
#define WARPS   8                    // 256 threads
#define TOK_PER_WARP (TOK / WARPS)   // 10

// Per-block projected partials: [chunk][batch][2]
__device__ float g_dots[NCHUNK * BATCH * OUTD];

// ---------------------------------------------------------------------------
// Kernel 1: gather + partial sum + [50 -> 2] projection.
// grid = (BATCH, NCHUNK), block = 256 (8 warps).
// Each warp owns 10 tokens; lanes 0-24 load the 50-float row as 25 float2.
// ---------------------------------------------------------------------------
__global__ __launch_bounds__(256)
void gather_kernel(const int* __restrict__ t,
                   const float* __restrict__ emb,
                   const float* __restrict__ W)
{
    const int b     = blockIdx.x;
    const int chunk = blockIdx.y;
    const int tid   = threadIdx.x;
    const int wid   = tid >> 5;
    const int lane  = tid & 31;

    __shared__ int    sidx[TOK];
    __shared__ float2 sred[WARPS][25];

    const int* tp = t + (size_t)b * SEQ + (size_t)chunk * TOK;
    if (tid < TOK) sidx[tid] = tp[tid];
    __syncthreads();

    const float2* __restrict__ emb2 = (const float2*)emb;

    float2 acc = make_float2(0.0f, 0.0f);
    if (lane < 25) {
        #pragma unroll
        for (int i = 0; i < TOK_PER_WARP; i++) {
            int idx = sidx[wid * TOK_PER_WARP + i];
            if (idx >= 0 && idx < VOCAB) {
                float2 v = __ldg(&emb2[(size_t)idx * 25 + lane]);
                acc.x += v.x;
                acc.y += v.y;
            }
        }
        sred[wid][lane] = acc;
    }
    __syncthreads();

    // Warp 0: reduce 8 warps, project onto the two W rows, warp-reduce, store.
    if (tid < 32) {
        float d0 = 0.0f, d1 = 0.0f;
        if (tid < 25) {
            float2 p = make_float2(0.0f, 0.0f);
            #pragma unroll
            for (int w = 0; w < WARPS; w++) {
                p.x += sred[w][tid].x;
                p.y += sred[w][tid].y;
            }
            d0 = p.x * W[2 * tid]      + p.y * W[2 * tid + 1];       // row 0
            d1 = p.x * W[EMB + 2*tid]  + p.y * W[EMB + 2*tid + 1];   // row 1
        }
        #pragma unroll
        for (int off = 16; off > 0; off >>= 1) {
            d0 += __shfl_down_sync(0xFFFFFFFFu, d0, off);
            d1 += __shfl_down_sync(0xFFFFFFFFu, d1, off);
        }
        if (tid == 0) {
            g_dots[((size_t)chunk * BATCH + b) * OUTD + 0] = d0;
            g_dots[((size_t)chunk * BATCH + b) * OUTD + 1] = d1;
        }
    }
}

// ---------------------------------------------------------------------------
// Kernel 2: sum chunk partials, /BATCH, +bias, ReLU.  1 block, 256 threads,
// thread tid handles (b = tid/2, o = tid%2).
// ---------------------------------------------------------------------------
__global__ void finalize_kernel(const float* __restrict__ bias,
                                float* __restrict__ out)
{
    const int tid = threadIdx.x;      // [0,256)
    const int o   = tid & 1;

    float s = 0.0f;
    #pragma unroll
    for (int k = 0; k < NCHUNK; k++) {
        s += g_dots[(size_t)k * BATCH * OUTD + tid];
    }
    out[tid] = fmaxf(s * (1.0f / (float)BATCH) + bias[o], 0.0f);
}

// ---------------------------------------------------------------------------
// Inputs: t [128,2000] int32, embeddings [1e6,50] f32, W [2,50] f32, b [2] f32.
// Output: [128,2] f32.
// ---------------------------------------------------------------------------
extern "C" void kernel_launch(void* const* d_in, const int* in_sizes, int n_in,
                              void* d_out, int out_size)
{
    const int*   t   = (const int*)d_in[0];
    const float* emb = (const float*)d_in[1];
    const float* W   = (const float*)d_in[2];
    const float* bia = (const float*)d_in[3];
    float*       out = (float*)d_out;

    dim3 grid1(BATCH, NCHUNK);
    gather_kernel<<<grid1, 256>>>(t, emb, W);

    finalize_kernel<<<1, BATCH * OUTD>>>(bia, out);
}